// round 13
// baseline (speedup 1.0000x reference)
#include <cuda_runtime.h>
#include <cuda_bf16.h>
#include <cuda_fp16.h>
#include <math.h>
#include <stdint.h>

// ---------------- problem constants ----------------
#define Hd    1024
#define HEADS 16
#define DHd   64
#define Wn    256
#define Rn    128
#define Id    4096
#define Bn    2
#define Sn    4096
#define NW    31
#define BNW   (Bn*NW)       // 62
#define Tn    (BNW*Wn)      // 15872

typedef unsigned long long ull;

// ---- arch-specific ('a' target) feature gate for tcgen05 ------------------
#if !defined(__CUDA_ARCH__) || defined(__CUDA_ARCH_FEAT_SM103_ALL) || \
    defined(__CUDA_ARCH_FEAT_SM100_ALL) || defined(__CUDA_ARCH_SPECIFIC__) || \
    defined(__CUDA_ARCH_FAMILY_SPECIFIC__)
#define TC_OK 1
#else
#define TC_OK 0
#endif

// ---------------- tcgen05 / mbarrier helpers -------------------------------
__device__ __forceinline__ uint32_t smem_u32(const void* p) {
    uint32_t a;
    asm("{ .reg .u64 t; cvta.to.shared.u64 t, %1; cvt.u32.u64 %0, t; }" : "=r"(a) : "l"(p));
    return a;
}
#define SWZ(o)   ((o) ^ (((o) >> 3) & 0x70))
#define SWZ64(o) ((o) ^ (((o) >> 3) & 0x30))

#define MBAR_INIT(a, c) asm volatile("mbarrier.init.shared.b64 [%0], %1;" :: "r"(a), "r"(c) : "memory")
#define MBAR_WAIT(a, p) do { uint32_t _m = (a), _p = (p), _d;                                            \
    asm volatile("{\n\t.reg .pred P;\n\tmbarrier.try_wait.parity.acquire.cta.shared::cta.b64 P, [%1], %2;\n\tselp.b32 %0,1,0,P;\n\t}" \
        : "=r"(_d) : "r"(_m), "r"(_p) : "memory");                                                        \
    while (!_d) {                                                                                          \
        asm volatile("{\n\t.reg .pred P;\n\tmbarrier.try_wait.parity.acquire.cta.shared::cta.b64 P, [%1], %2, 0x989680;\n\tselp.b32 %0,1,0,P;\n\t}" \
            : "=r"(_d) : "r"(_m), "r"(_p) : "memory");                                                    \
    } } while (0)

// cp.async (LDGSTS) helpers
__device__ __forceinline__ void cp16(uint32_t dst, const void* src) {
    asm volatile("cp.async.cg.shared.global [%0], [%1], 16;" :: "r"(dst), "l"(src) : "memory");
}
#define CPA_ARRIVE(a) asm volatile("cp.async.mbarrier.arrive.noinc.shared::cta.b64 [%0];" :: "r"(a) : "memory")

#if TC_OK
#define TC_ALLOC(slot, n)  asm volatile("tcgen05.alloc.cta_group::1.sync.aligned.shared::cta.b32 [%0], %1;" :: "r"(slot), "r"(n) : "memory")
#define TC_DEALLOC(t, n)   asm volatile("tcgen05.dealloc.cta_group::1.sync.aligned.b32 %0, %1;" :: "r"(t), "r"(n))
#define TC_RELINQ()        asm volatile("tcgen05.relinquish_alloc_permit.cta_group::1.sync.aligned;")
#define TC_COMMIT(m)       asm volatile("tcgen05.commit.cta_group::1.mbarrier::arrive::one.shared::cluster.b64 [%0];" :: "r"(m) : "memory")
#define TC_FENCE_AFTER()   asm volatile("tcgen05.fence::after_thread_sync;" ::: "memory")
#define TC_FENCE_BEFORE()  asm volatile("tcgen05.fence::before_thread_sync;" ::: "memory")
#define TC_WAIT_LD()       asm volatile("tcgen05.wait::ld.sync.aligned;" ::: "memory")
#define TC_WAIT_ST()       asm volatile("tcgen05.wait::st.sync.aligned;" ::: "memory")
#define TC_LD_X32(r, a) \
    asm volatile("tcgen05.ld.sync.aligned.32x32b.x32.b32 " \
        "{%0,%1,%2,%3,%4,%5,%6,%7,%8,%9,%10,%11,%12,%13,%14,%15," \
        "%16,%17,%18,%19,%20,%21,%22,%23,%24,%25,%26,%27,%28,%29,%30,%31}, [%32];" \
        : "=r"((r)[0]),"=r"((r)[1]),"=r"((r)[2]),"=r"((r)[3]),"=r"((r)[4]),"=r"((r)[5]),"=r"((r)[6]),"=r"((r)[7]), \
          "=r"((r)[8]),"=r"((r)[9]),"=r"((r)[10]),"=r"((r)[11]),"=r"((r)[12]),"=r"((r)[13]),"=r"((r)[14]),"=r"((r)[15]), \
          "=r"((r)[16]),"=r"((r)[17]),"=r"((r)[18]),"=r"((r)[19]),"=r"((r)[20]),"=r"((r)[21]),"=r"((r)[22]),"=r"((r)[23]), \
          "=r"((r)[24]),"=r"((r)[25]),"=r"((r)[26]),"=r"((r)[27]),"=r"((r)[28]),"=r"((r)[29]),"=r"((r)[30]),"=r"((r)[31]) \
        : "r"(a))
#define TC_ST_X32(a, r) \
    asm volatile("tcgen05.st.sync.aligned.32x32b.x32.b32 [%0], " \
        "{%1,%2,%3,%4,%5,%6,%7,%8,%9,%10,%11,%12,%13,%14,%15,%16," \
        "%17,%18,%19,%20,%21,%22,%23,%24,%25,%26,%27,%28,%29,%30,%31,%32};" \
        :: "r"(a), \
           "r"((r)[0]),"r"((r)[1]),"r"((r)[2]),"r"((r)[3]),"r"((r)[4]),"r"((r)[5]),"r"((r)[6]),"r"((r)[7]), \
           "r"((r)[8]),"r"((r)[9]),"r"((r)[10]),"r"((r)[11]),"r"((r)[12]),"r"((r)[13]),"r"((r)[14]),"r"((r)[15]), \
           "r"((r)[16]),"r"((r)[17]),"r"((r)[18]),"r"((r)[19]),"r"((r)[20]),"r"((r)[21]),"r"((r)[22]),"r"((r)[23]), \
           "r"((r)[24]),"r"((r)[25]),"r"((r)[26]),"r"((r)[27]),"r"((r)[28]),"r"((r)[29]),"r"((r)[30]),"r"((r)[31]) \
        : "memory")
#else
#define TC_ALLOC(slot, n)  do {} while (0)
#define TC_DEALLOC(t, n)   do {} while (0)
#define TC_RELINQ()        do {} while (0)
#define TC_COMMIT(m)       do {} while (0)
#define TC_FENCE_AFTER()   do {} while (0)
#define TC_FENCE_BEFORE()  do {} while (0)
#define TC_WAIT_LD()       do {} while (0)
#define TC_WAIT_ST()       do {} while (0)
#define TC_LD_X32(r, a)    do { _Pragma("unroll") for (int _i = 0; _i < 32; _i++) (r)[_i] = 0u; } while (0)
#define TC_ST_X32(a, r)    do { (void)(a); (void)(r)[0]; } while (0)
#endif
#define FENCE_ASYNC()      asm volatile("fence.proxy.async.shared::cta;" ::: "memory")

__device__ __forceinline__ void mma_ss_f16(uint32_t d, ull ad, ull bd, uint32_t idesc, int acc) {
#if TC_OK
    asm volatile("{\n\t.reg .pred p;\n\tsetp.ne.u32 p, %5, 0;\n\t"
        "tcgen05.mma.cta_group::1.kind::f16 [%0], %1, %2, %3, {%4,%4,%4,%4}, p;\n\t}"
        :: "r"(d), "l"(ad), "l"(bd), "r"(idesc), "r"(0u), "r"(acc) : "memory");
#endif
}
__device__ __forceinline__ void mma_ts_f16(uint32_t d, uint32_t a, ull bd, uint32_t idesc, int acc) {
#if TC_OK
    asm volatile("{\n\t.reg .pred p;\n\tsetp.ne.u32 p, %5, 0;\n\t"
        "tcgen05.mma.cta_group::1.kind::f16 [%0], [%1], %2, %3, {%4,%4,%4,%4}, p;\n\t}"
        :: "r"(d), "r"(a), "l"(bd), "r"(idesc), "r"(0u), "r"(acc) : "memory");
#endif
}

// SW128 K-major smem descriptor (LBO=1, SBO=64)
static __device__ __forceinline__ ull make_desc(uint32_t addr) {
    return (2ULL << 61) | (1ULL << 46) | (64ULL << 32) | (1ULL << 16)
         | ((ull)(addr >> 4) & 0x3FFF);
}
// SW64 K-major smem descriptor (LBO=1, SBO=32, layout=4) — validated R9
static __device__ __forceinline__ ull make_desc64(uint32_t addr) {
    return (4ULL << 61) | (1ULL << 46) | (32ULL << 32) | (1ULL << 16)
         | ((ull)(addr >> 4) & 0x3FFF);
}

__device__ __forceinline__ void bfsplit2(float a, float b, uint32_t& h, uint32_t& l) {
    __nv_bfloat162 hh, ll;
    hh.x = __float2bfloat16(a); hh.y = __float2bfloat16(b);
    ll.x = __float2bfloat16(a - __bfloat162float(hh.x));
    ll.y = __float2bfloat16(b - __bfloat162float(hh.y));
    h = *(uint32_t*)&hh; l = *(uint32_t*)&ll;
}

// ---------------- scratch --------------------------------------------------
__device__ float g_qkv[(size_t)Tn * 3 * Hd];
__device__ float g_y  [(size_t)Tn * Hd];
__device__ float g_yf [(size_t)Tn * Hd];
__device__ __nv_bfloat16 g_nh[(size_t)Tn * Hd], g_nl[(size_t)Tn * Hd];
__device__ __nv_bfloat16 g_oh[(size_t)Tn * Hd], g_ol[(size_t)Tn * Hd];
__device__ __nv_bfloat16 g_ch[(size_t)Tn * Id], g_cl[(size_t)Tn * Id];
__device__ __nv_bfloat16 g_wh[(size_t)2 * Id * Hd], g_wl[(size_t)2 * Id * Hd];

// ---------------- split fp32 -> bf16 hi/lo ---------------------------------
__global__ void split_kernel(const float* __restrict__ in,
                             __nv_bfloat16* __restrict__ hi,
                             __nv_bfloat16* __restrict__ lo, long n) {
    long i = (long)blockIdx.x * 256 + threadIdx.x;
    if (i < n) {
        float v = in[i];
        __nv_bfloat16 h = __float2bfloat16(v);
        hi[i] = h;
        lo[i] = __float2bfloat16(v - __bfloat162float(h));
    }
}

// split gate_up weights with row interleave: out row 2i=gate_i, 2i+1=up_i
__global__ void split_gu_kernel(const float* __restrict__ in,
                                __nv_bfloat16* __restrict__ hi,
                                __nv_bfloat16* __restrict__ lo) {
    long i = (long)blockIdx.x * 256 + threadIdx.x;    // over 2*Id*Hd
    if (i < (long)2 * Id * Hd) {
        int row = (int)(i >> 10), col = (int)(i & (Hd - 1));
        int src = (row & 1) ? (Id + (row >> 1)) : (row >> 1);
        float v = in[(size_t)src * Hd + col];
        __nv_bfloat16 h = __float2bfloat16(v);
        hi[i] = h;
        lo[i] = __float2bfloat16(v - __bfloat162float(h));
    }
}

// ---------------- RMSNorm (optional window gather), writes bf16 split -----
template<bool GATHER>
__global__ void rmsnorm_kernel(const float* __restrict__ src,
                               const float* __restrict__ w,
                               __nv_bfloat16* __restrict__ oh,
                               __nv_bfloat16* __restrict__ ol) {
    int t = blockIdx.x;
    const float* row;
    if (GATHER) {
        int bn = t >> 8, ww = t & 255;
        int b = bn / NW, n = bn - b * NW;
        row = src + (size_t)(b * Sn + n * Rn + ww) * Hd;
    } else {
        row = src + (size_t)t * Hd;
    }
    int tid = threadIdx.x;
    float ss = 0.f;
    for (int h = tid; h < Hd; h += 256) { float v = row[h]; ss += v * v; }
    __shared__ float red[8];
    #pragma unroll
    for (int o = 16; o; o >>= 1) ss += __shfl_xor_sync(~0u, ss, o);
    if ((tid & 31) == 0) red[tid >> 5] = ss;
    __syncthreads();
    if (tid < 8) {
        float v = red[tid];
        #pragma unroll
        for (int o = 4; o; o >>= 1) v += __shfl_xor_sync(0xff, v, o);
        if (tid == 0) red[0] = v;
    }
    __syncthreads();
    float rms = rsqrtf(red[0] * (1.f / Hd) + 1e-5f);
    for (int h = tid; h < Hd; h += 256) {
        float v = row[h] * rms * w[h];
        __nv_bfloat16 hv = __float2bfloat16(v);
        oh[(size_t)t * Hd + h] = hv;
        ol[(size_t)t * Hd + h] = __float2bfloat16(v - __bfloat162float(hv));
    }
}

// ---------------- tcgen05 bf16-split GEMM: 256x256, Kc=32, mbarrier pipe ---
// EPI: 0 none, 1 +=Res, 2 +=gathered x, 3 swiglu->bf16 split, 4 rope on q/k
// Buffer (64KB): Ah@0(16K) Al@16K Bh@32K(16K) Bl@48K(16K). 3 buffers = 192KB.
// mbars: full[s]=sb+8+8s (count 128, cp.async.mbarrier.arrive.noinc),
//        done[s]=sb+32+8s (count 1, tcgen05 commit). NO __syncthreads in loop.
// Prologue loads chunks 0,1 ONLY; mainloop prefetches c+2 (slot fresh at c=0).
#define GBUF  65536
#define GSMEM (1024 + 3 * GBUF)

__device__ __forceinline__ void bg_load32(
    const __nv_bfloat16* Ah, const __nv_bfloat16* Al,
    const __nv_bfloat16* Bh, const __nv_bfloat16* Bl,
    int bm, int bn, int K, int k0, uint32_t stu, int tid) {
    const int strideA = K >> 3;                 // uint4 per row
    {
        const uint4* gh = (const uint4*)(Ah + (size_t)bm * K + k0);
        const uint4* gl = (const uint4*)(Al + (size_t)bm * K + k0);
        #pragma unroll
        for (int it = 0; it < 8; it++) {
            int v = (it << 7) + tid;            // 0..1023
            int row = v >> 2, c16 = v & 3;      // 256 rows x 4 uint4
            uint32_t so = SWZ64(row * 64 + c16 * 16);
            cp16(stu + so,         gh + (size_t)row * strideA + c16);
            cp16(stu + 16384 + so, gl + (size_t)row * strideA + c16);
        }
    }
    {
        const uint4* gh = (const uint4*)(Bh + (size_t)bn * K + k0);
        const uint4* gl = (const uint4*)(Bl + (size_t)bn * K + k0);
        #pragma unroll
        for (int it = 0; it < 8; it++) {
            int v = (it << 7) + tid;
            int row = v >> 2, c16 = v & 3;
            uint32_t so = SWZ64(row * 64 + c16 * 16);
            cp16(stu + 32768 + so, gh + (size_t)row * strideA + c16);
            cp16(stu + 49152 + so, gl + (size_t)row * strideA + c16);
        }
    }
}

template<int EPI>
__global__ void __launch_bounds__(128, 1)
bgemm_kernel(const __nv_bfloat16* __restrict__ Ah, const __nv_bfloat16* __restrict__ Al,
             const __nv_bfloat16* __restrict__ Bh, const __nv_bfloat16* __restrict__ Bl,
             float* __restrict__ C, const float* __restrict__ Res,
             __nv_bfloat16* __restrict__ Oh, __nv_bfloat16* __restrict__ Ol,
             const int* __restrict__ pos, int Nc, int K) {
    extern __shared__ __align__(1024) char smem[];
    const int tid = threadIdx.x, wid = tid >> 5, lid = tid & 31;
    const int bm = blockIdx.y << 8, bn = blockIdx.x << 8;
    uint32_t sb = smem_u32(smem);

    if (tid == 0) {
        #pragma unroll
        for (int s = 0; s < 3; s++) {
            MBAR_INIT(sb + 8 + 8 * s, 128);     // full: all threads' cp.async
            MBAR_INIT(sb + 32 + 8 * s, 1);      // done: MMA commit
        }
    }
    if (wid == 0) TC_ALLOC(sb, 512);
    __syncthreads();
    uint32_t tmem;
    asm("ld.shared.b32 %0, [%1];" : "=r"(tmem) : "r"(sb));

    // f16 kind, bf16 in, f32 out, N=256, M=128
    const uint32_t IDESC = (1u << 4) | (1u << 7) | (1u << 10) | (32u << 17) | (8u << 24);
    const int KCn = K >> 5;                    // Kc = 32 (KCn >= 32 always)

    // prologue: chunks 0,1 -> slots 0,1 (chunk 2 is prefetched at c==0)
    #pragma unroll
    for (int s = 0; s < 2; s++) {
        bg_load32(Ah, Al, Bh, Bl, bm, bn, K, s << 5, sb + 1024 + s * GBUF, tid);
        CPA_ARRIVE(sb + 8 + 8 * s);
    }

    #pragma unroll 1
    for (int c = 0; c < KCn; c++) {
        int s = c - (c / 3) * 3;
        uint32_t stu = sb + 1024 + s * GBUF;
        if (tid == 0) {
            MBAR_WAIT(sb + 8 + 8 * s, (uint32_t)(c / 3) & 1);
            FENCE_ASYNC();
            ull dAh = make_desc64(stu);
            ull dAl = make_desc64(stu + 16384);
            ull dBh = make_desc64(stu + 32768);
            ull dBl = make_desc64(stu + 49152);
            #pragma unroll
            for (int t = 0; t < 2; t++) {
                uint32_t D = tmem + (t << 8);
                ull at = (ull)(t * 512);        // Mtile1 rows at +8192B
                #pragma unroll
                for (int ks = 0; ks < 2; ks++) {
                    ull ao = at + ks * 2;
                    ull bo = (ull)(ks * 2);
                    int first = (c == 0 && ks == 0) ? 0 : 1;
                    mma_ss_f16(D, dAh + ao, dBh + bo, IDESC, first);
                    mma_ss_f16(D, dAh + ao, dBl + bo, IDESC, 1);
                    mma_ss_f16(D, dAl + ao, dBh + bo, IDESC, 1);
                }
            }
            TC_COMMIT(sb + 32 + 8 * s);
        }
        // producers (all threads): prefetch chunk c+2 into slot (c+2)%3.
        // At c==0 that slot is fresh; for c>=1 it last held chunk c-1 ->
        // wait chunk c-1's MMA commit before overwriting.
        if (c + 2 < KCn) {
            int m = c - 1;
            int s2 = (c + 2) - ((c + 2) / 3) * 3;
            if (m >= 0) MBAR_WAIT(sb + 32 + 8 * s2, (uint32_t)(m / 3) & 1);
            bg_load32(Ah, Al, Bh, Bl, bm, bn, K, (c + 2) << 5,
                      sb + 1024 + s2 * GBUF, tid);
            CPA_ARRIVE(sb + 8 + 8 * s2);
        }
    }
    // all threads: wait final chunk's commit (covers all prior MMAs)
    {
        int last = KCn - 1;
        MBAR_WAIT(sb + 32 + 8 * (last - (last / 3) * 3), (uint32_t)(last / 3) & 1);
    }
    TC_FENCE_AFTER();

    // epilogue: 2 Mtiles x (4 warps x 32 rows); N=256 in 8 groups of 32
    #pragma unroll 1
    for (int t = 0; t < 2; t++) {
        int row = bm + (t << 7) + (wid << 5) + lid;
        if (EPI == 4) {
            float snt[32], cst[32];
            {
                int bnw = row >> 8, ww = row & 255;
                int b = bnw / NW, n = bnw - b * NW;
                float p = (float)pos[b * Sn + n * Rn + ww];
                #pragma unroll
                for (int d = 0; d < 32; d++) {
                    float inv = powf(10000.f, -(2.f * d) / 64.f);
                    sincosf(p * inv, &snt[d], &cst[d]);
                }
            }
            float* cbase = C + (size_t)row * Nc + bn;
            #pragma unroll 1
            for (int hh = 0; hh < 4; hh++) {
                uint32_t r0[32], r1[32];
                TC_LD_X32(r0, tmem + (t << 8) + hh * 64);
                TC_LD_X32(r1, tmem + (t << 8) + hh * 64 + 32);
                TC_WAIT_LD();
                float a[32], b[32];
                #pragma unroll
                for (int j = 0; j < 32; j++) { a[j] = __uint_as_float(r0[j]); b[j] = __uint_as_float(r1[j]); }
                if (bn + hh * 64 < 2048) {
                    #pragma unroll
                    for (int d = 0; d < 32; d++) {
                        float q1 = a[d], q2 = b[d];
                        a[d] = q1 * cst[d] - q2 * snt[d];
                        b[d] = q2 * cst[d] + q1 * snt[d];
                    }
                }
                #pragma unroll
                for (int j = 0; j < 32; j += 4) {
                    float4 o0 = {a[j], a[j+1], a[j+2], a[j+3]};
                    float4 o1 = {b[j], b[j+1], b[j+2], b[j+3]};
                    *(float4*)(cbase + hh * 64 + j) = o0;
                    *(float4*)(cbase + hh * 64 + 32 + j) = o1;
                }
            }
        } else if (EPI == 3) {
            int outb = (bn >> 1);
            __nv_bfloat16* chb = Oh + (size_t)row * Id + outb;
            __nv_bfloat16* clb = Ol + (size_t)row * Id + outb;
            #pragma unroll 1
            for (int g = 0; g < 8; g++) {
                uint32_t r[32];
                TC_LD_X32(r, tmem + (t << 8) + g * 32);
                TC_WAIT_LD();
                __nv_bfloat162 ph[8], pl[8];
                #pragma unroll
                for (int m = 0; m < 16; m++) {
                    float gv = __uint_as_float(r[2 * m]);
                    float uv = __uint_as_float(r[2 * m + 1]);
                    float v = uv * (gv / (1.f + expf(-gv)));
                    __nv_bfloat16 hv = __float2bfloat16(v);
                    ((__nv_bfloat16*)ph)[m] = hv;
                    ((__nv_bfloat16*)pl)[m] = __float2bfloat16(v - __bfloat162float(hv));
                }
                #pragma unroll
                for (int m2 = 0; m2 < 8; m2++) {
                    ((__nv_bfloat162*)(chb + g * 16))[m2] = ph[m2];
                    ((__nv_bfloat162*)(clb + g * 16))[m2] = pl[m2];
                }
            }
        } else {
            const float* rbase = nullptr;
            if (EPI == 1) rbase = Res + (size_t)row * Nc + bn;
            if (EPI == 2) {
                int bnw = row >> 8, ww = row & 255;
                int b = bnw / NW, n = bnw - b * NW;
                rbase = Res + (size_t)(b * Sn + n * Rn + ww) * Hd + bn;
            }
            float* cbase = C + (size_t)row * Nc + bn;
            #pragma unroll 1
            for (int g = 0; g < 8; g++) {
                uint32_t r[32];
                TC_LD_X32(r, tmem + (t << 8) + g * 32);
                TC_WAIT_LD();
                float rv[32];
                #pragma unroll
                for (int j = 0; j < 32; j++) rv[j] = __uint_as_float(r[j]);
                if (EPI) {
                    #pragma unroll
                    for (int j = 0; j < 32; j++) rv[j] += rbase[g * 32 + j];
                }
                #pragma unroll
                for (int j = 0; j < 32; j += 4) {
                    float4 o = {rv[j], rv[j+1], rv[j+2], rv[j+3]};
                    *(float4*)(cbase + g * 32 + j) = o;
                }
            }
        }
    }
    __syncthreads();
    if (wid == 0) { TC_RELINQ(); TC_DEALLOC(tmem, 512); }
}

// ---------------- tensor-core windowed causal attention --------------------
#define AQH  1024
#define AQL  (AQH + 32768)
#define AKH  (AQL + 32768)
#define AKL  (AKH + 32768)
#define AVH  (AKL + 32768)
#define AVL  (AVH + 32768)
#define AQQ  (AVL + 32768)            // 256 floats
#define AKN  (AQQ + 1024)             // 8 floats
#define ATTN_SMEM (AKN + 64)

__global__ void __launch_bounds__(256, 1)
attn_kernel(const float* __restrict__ qkv,
            __nv_bfloat16* __restrict__ outh, __nv_bfloat16* __restrict__ outl) {
    int bnw = blockIdx.x, h = blockIdx.y;
    extern __shared__ __align__(1024) char smem[];
    uint32_t sb = smem_u32(smem);
    int tid = threadIdx.x, wid = tid >> 5, lid = tid & 31;
    int t0 = bnw * Wn;
    float* qqA = (float*)(smem + AQQ);
    float* knW = (float*)(smem + AKN);

    if (tid == 0) { MBAR_INIT(sb + 8, 1); MBAR_INIT(sb + 16, 1); }
    if (wid == 0) TC_ALLOC(sb, 512);
    __syncthreads();
    uint32_t tmem;
    asm("ld.shared.b32 %0, [%1];" : "=r"(tmem) : "r"(sb));

    {
        const float4* qrow = (const float4*)(qkv + (size_t)(t0 + tid) * (3 * Hd) + h * DHd);
        const float4* krow = qrow + (Hd / 4);
        const float4* vrow = qrow + (2 * Hd / 4);
        float qq = 0.f, kk = 0.f;
        #pragma unroll
        for (int g = 0; g < 8; g++) {
            float4 a = qrow[g * 2], b = qrow[g * 2 + 1];
            qq += a.x*a.x + a.y*a.y + a.z*a.z + a.w*a.w + b.x*b.x + b.y*b.y + b.z*b.z + b.w*b.w;
            uint4 hi, lo;
            bfsplit2(a.x, a.y, hi.x, lo.x); bfsplit2(a.z, a.w, hi.y, lo.y);
            bfsplit2(b.x, b.y, hi.z, lo.z); bfsplit2(b.z, b.w, hi.w, lo.w);
            uint32_t so = SWZ(tid * 128 + g * 16);
            *(uint4*)(smem + AQH + so) = hi;
            *(uint4*)(smem + AQL + so) = lo;
        }
        #pragma unroll
        for (int g = 0; g < 8; g++) {
            float4 a = krow[g * 2], b = krow[g * 2 + 1];
            kk += a.x*a.x + a.y*a.y + a.z*a.z + a.w*a.w + b.x*b.x + b.y*b.y + b.z*b.z + b.w*b.w;
            uint4 hi, lo;
            bfsplit2(a.x, a.y, hi.x, lo.x); bfsplit2(a.z, a.w, hi.y, lo.y);
            bfsplit2(b.x, b.y, hi.z, lo.z); bfsplit2(b.z, b.w, hi.w, lo.w);
            uint32_t so = SWZ(tid * 128 + g * 16);
            *(uint4*)(smem + AKH + so) = hi;
            *(uint4*)(smem + AKL + so) = lo;
        }
        char* vhB = smem + AVH + (tid >> 6) * 8192;
        char* vlB = smem + AVL + (tid >> 6) * 8192;
        int jj2 = (tid & 63) * 2;
        #pragma unroll
        for (int d4 = 0; d4 < 16; d4++) {
            float4 v = vrow[d4];
            float vv[4] = {v.x, v.y, v.z, v.w};
            #pragma unroll
            for (int e = 0; e < 4; e++) {
                int d = d4 * 4 + e;
                __half hh = __float2half_rn(vv[e]);
                __half hl = __float2half_rn(vv[e] - __half2float(hh));
                *(__half*)(vhB + SWZ(d * 128 + jj2)) = hh;
                *(__half*)(vlB + SWZ(d * 128 + jj2)) = hl;
            }
        }
        qqA[tid] = qq;
        #pragma unroll
        for (int o = 16; o; o >>= 1) kk = fmaxf(kk, __shfl_xor_sync(~0u, kk, o));
        if (lid == 0) knW[wid] = kk;
    }
    __syncthreads();

    if (tid == 0) {
        FENCE_ASYNC();
        ull qh = make_desc(sb + AQH), ql = make_desc(sb + AQL);
        ull kh = make_desc(sb + AKH), kl = make_desc(sb + AKL);
        const uint32_t IDS = (1u << 4) | (1u << 7) | (1u << 10) | (16u << 17) | (8u << 24);
        #pragma unroll
        for (int t = 0; t < 2; t++) {
            #pragma unroll
            for (int n = 0; n < 2; n++) {
                uint32_t D = tmem + t * 256 + n * 128;
                #pragma unroll
                for (int ks = 0; ks < 4; ks++) {
                    ull ao = (ull)(t * 1024 + ks * 2);
                    ull bo = (ull)(n * 1024 + ks * 2);
                    mma_ss_f16(D, qh + ao, kh + bo, IDS, ks > 0);
                    mma_ss_f16(D, qh + ao, kl + bo, IDS, 1);
                    mma_ss_f16(D, ql + ao, kh + bo, IDS, 1);
                }
            }
        }
        TC_COMMIT(sb + 8);
    }
    MBAR_WAIT(sb + 8, 0);
    TC_FENCE_AFTER();

    int t = wid >> 2;
    int qi = t * 128 + (wid & 3) * 32 + lid;
    float KM = knW[0];
    #pragma unroll
    for (int w = 1; w < 8; w++) KM = fmaxf(KM, knW[w]);
    float mx = sqrtf(qqA[qi] * KM) * 0.125f;
    float l = 0.f;
    uint32_t woff = (uint32_t)(wid & 3) << 21;
    #pragma unroll 1
    for (int c = 0; c < 4; c++) {
        uint32_t r0[32], r1[32];
        TC_LD_X32(r0, tmem + t * 256 + c * 64);
        TC_LD_X32(r1, tmem + t * 256 + c * 64 + 32);
        TC_WAIT_LD();
        float pa[64];
        #pragma unroll
        for (int i = 0; i < 32; i++) {
            float s = __uint_as_float(r0[i]);
            float p = __expf(fmaf(s, 0.125f, -mx));
            p = (c * 64 + i <= qi) ? p : 0.f;
            l += p; pa[i] = p;
        }
        #pragma unroll
        for (int i = 0; i < 32; i++) {
            float s = __uint_as_float(r1[i]);
            float p = __expf(fmaf(s, 0.125f, -mx));
            p = (c * 64 + 32 + i <= qi) ? p : 0.f;
            l += p; pa[32 + i] = p;
        }
        uint32_t pr[32];
        #pragma unroll
        for (int i = 0; i < 32; i++) {
            __half2 h2 = __float22half2_rn(make_float2(pa[2 * i], pa[2 * i + 1]));
            pr[i] = *(uint32_t*)&h2;
        }
        TC_ST_X32(tmem + t * 256 + c * 32 + woff, pr);
    }
    TC_WAIT_ST();
    TC_FENCE_BEFORE();
    __syncthreads();

    if (tid == 0) {
        TC_FENCE_AFTER();
        ull vh = make_desc(sb + AVH), vl = make_desc(sb + AVL);
        const uint32_t IDP = (1u << 4) | (8u << 17) | (8u << 24);
        #pragma unroll
        for (int tt = 0; tt < 2; tt++) {
            uint32_t D = tmem + tt * 256 + 128;
            #pragma unroll
            for (int s = 0; s < 16; s++) {
                ull bo = (ull)((s >> 2) * 512 + (s & 3) * 2);
                uint32_t A = tmem + tt * 256 + s * 8;
                mma_ts_f16(D, A, vh + bo, IDP, s > 0);
                mma_ts_f16(D, A, vl + bo, IDP, 1);
            }
        }
        TC_COMMIT(sb + 16);
    }
    MBAR_WAIT(sb + 16, 0);
    TC_FENCE_AFTER();

    {
        uint32_t o0[32], o1[32];
        TC_LD_X32(o0, tmem + t * 256 + 128);
        TC_LD_X32(o1, tmem + t * 256 + 160);
        TC_WAIT_LD();
        float inv = 1.f / l;
        uint32_t* ohp = (uint32_t*)(outh + (size_t)(t0 + qi) * Hd + h * DHd);
        uint32_t* olp = (uint32_t*)(outl + (size_t)(t0 + qi) * Hd + h * DHd);
        #pragma unroll
        for (int i = 0; i < 16; i++) {
            uint32_t hu, lu;
            bfsplit2(__uint_as_float(o0[2 * i]) * inv, __uint_as_float(o0[2 * i + 1]) * inv, hu, lu);
            ohp[i] = hu; olp[i] = lu;
        }
        #pragma unroll
        for (int i = 0; i < 16; i++) {
            uint32_t hu, lu;
            bfsplit2(__uint_as_float(o1[2 * i]) * inv, __uint_as_float(o1[2 * i + 1]) * inv, hu, lu);
            ohp[16 + i] = hu; olp[16 + i] = lu;
        }
    }
    __syncthreads();
    if (wid == 0) { TC_RELINQ(); TC_DEALLOC(tmem, 512); }
}

// ---------------- per-window attn-pool -------------------------------------
__global__ void pool_kernel(const float* __restrict__ y, const float* __restrict__ sw,
                            float* __restrict__ z) {
    int bn = blockIdx.x, tid = threadIdx.x;
    __shared__ float alpha[256];
    __shared__ float tmp[256];
    const float4* row = (const float4*)(y + (size_t)(bn * Wn + tid) * Hd);
    const float4* wv = (const float4*)sw;
    float s = 0.f;
    for (int i = 0; i < Hd / 4; i++) {
        float4 a = row[i], b = wv[i];
        s += a.x * b.x + a.y * b.y + a.z * b.z + a.w * b.w;
    }
    tmp[tid] = s; __syncthreads();
    for (int o = 128; o; o >>= 1) { if (tid < o) tmp[tid] = fmaxf(tmp[tid], tmp[tid + o]); __syncthreads(); }
    float mx = tmp[0]; __syncthreads();
    float e = expf(s - mx);
    tmp[tid] = e; __syncthreads();
    for (int o = 128; o; o >>= 1) { if (tid < o) tmp[tid] += tmp[tid + o]; __syncthreads(); }
    alpha[tid] = e / tmp[0];
    __syncthreads();
    for (int hh = tid; hh < Hd; hh += 256) {
        float a = 0.f;
        for (int w2 = 0; w2 < Wn; w2++)
            a = fmaf(alpha[w2], y[(size_t)(bn * Wn + w2) * Hd + hh], a);
        z[(size_t)bn * Hd + hh] = a;
    }
}

// ---------------- triangular overlap-add stitch ----------------------------
__global__ void stitch_kernel(const float* __restrict__ yf, float* __restrict__ out) {
    size_t id = (size_t)blockIdx.x * 256 + threadIdx.x;
    int hcol = (int)(id & (Hd - 1));
    int s = (int)((id >> 10) & (Sn - 1));
    int b = (int)(id >> 22);
    int nhi = min(NW - 1, s >> 7);
    int nlo = max(0, (s - Rn) >> 7);
    float acc = 0.f, wsum = 0.f;
    for (int n = nlo; n <= nhi; n++) {
        int w2 = s - n * Rn;
        float blend = (w2 < 128 ? (float)w2 : (float)(256 - w2)) * (1.f / 128.f);
        acc = fmaf(blend, yf[(size_t)((b * NW + n) * Wn + w2) * Hd + hcol], acc);
        wsum += blend;
    }
    out[id] = acc / (wsum + 1e-8f);
}

__global__ void bp_kernel(float* out) {
    int i = threadIdx.x;
    if (i < BNW) out[i] = (float)((i % NW) * Rn + (Wn - 1));
}

// ---------------- launcher --------------------------------------------------
extern "C" void kernel_launch(void* const* d_in, const int* in_sizes, int n_in,
                              void* d_out, int out_size) {
    const float* x          = (const float*)d_in[0];
    const int*   pos        = (const int*)  d_in[1];
    const float* in_norm_w  = (const float*)d_in[2];
    const float* mlp_norm_w = (const float*)d_in[3];
    const float* qkv_w      = (const float*)d_in[4];
    const float* o_w        = (const float*)d_in[5];
    const float* gate_up_w  = (const float*)d_in[6];
    const float* down_w     = (const float*)d_in[7];
    const float* scorer_w   = (const float*)d_in[8];
    float* out = (float*)d_out;

    float *qkv, *y, *yf;
    __nv_bfloat16 *nh, *nl, *oh, *ol, *ch, *cl, *wh, *wl;
    cudaGetSymbolAddress((void**)&qkv, g_qkv);
    cudaGetSymbolAddress((void**)&y,   g_y);
    cudaGetSymbolAddress((void**)&yf,  g_yf);
    cudaGetSymbolAddress((void**)&nh,  g_nh);
    cudaGetSymbolAddress((void**)&nl,  g_nl);
    cudaGetSymbolAddress((void**)&oh,  g_oh);
    cudaGetSymbolAddress((void**)&ol,  g_ol);
    cudaGetSymbolAddress((void**)&ch,  g_ch);
    cudaGetSymbolAddress((void**)&cl,  g_cl);
    cudaGetSymbolAddress((void**)&wh,  g_wh);
    cudaGetSymbolAddress((void**)&wl,  g_wl);

    cudaFuncSetAttribute(attn_kernel, cudaFuncAttributeMaxDynamicSharedMemorySize, ATTN_SMEM);
    cudaFuncSetAttribute(bgemm_kernel<1>, cudaFuncAttributeMaxDynamicSharedMemorySize, GSMEM);
    cudaFuncSetAttribute(bgemm_kernel<2>, cudaFuncAttributeMaxDynamicSharedMemorySize, GSMEM);
    cudaFuncSetAttribute(bgemm_kernel<3>, cudaFuncAttributeMaxDynamicSharedMemorySize, GSMEM);
    cudaFuncSetAttribute(bgemm_kernel<4>, cudaFuncAttributeMaxDynamicSharedMemorySize, GSMEM);

    const int MB = Tn / 256;   // 62

    // 1) gather + input RMSNorm -> split
    rmsnorm_kernel<true><<<Tn, 256>>>(x, in_norm_w, nh, nl);
    // 2) QKV projection + fused RoPE
    split_kernel<<<(3 * Hd * Hd + 255) / 256, 256>>>(qkv_w, wh, wl, (long)3 * Hd * Hd);
    bgemm_kernel<4><<<dim3(3 * Hd / 256, MB), 128, GSMEM>>>(nh, nl, wh, wl, qkv, nullptr, nullptr, nullptr, pos, 3 * Hd, Hd);
    // 3) tensor-core attention -> split
    attn_kernel<<<dim3(BNW, HEADS), 256, ATTN_SMEM>>>(qkv, oh, ol);
    // 4) O projection + residual(gathered x)
    split_kernel<<<(Hd * Hd + 255) / 256, 256>>>(o_w, wh, wl, (long)Hd * Hd);
    bgemm_kernel<2><<<dim3(Hd / 256, MB), 128, GSMEM>>>(oh, ol, wh, wl, y, x, nullptr, nullptr, nullptr, Hd, Hd);
    // 5) MLP RMSNorm -> split
    rmsnorm_kernel<false><<<Tn, 256>>>(y, mlp_norm_w, nh, nl);
    // 6) gate_up (interleaved rows) + fused SwiGLU -> bf16 split act
    split_gu_kernel<<<(2 * Id * Hd + 255) / 256, 256>>>(gate_up_w, wh, wl);
    bgemm_kernel<3><<<dim3(2 * Id / 256, MB), 128, GSMEM>>>(nh, nl, wh, wl, nullptr, nullptr, ch, cl, nullptr, 2 * Id, Hd);
    // 7) down + residual(y)
    split_kernel<<<(Hd * Id + 255) / 256, 256>>>(down_w, wh, wl, (long)Hd * Id);
    bgemm_kernel<1><<<dim3(Hd / 256, MB), 128, GSMEM>>>(ch, cl, wh, wl, yf, y, nullptr, nullptr, nullptr, Hd, Id);

    const size_t YL = (size_t)Bn * Sn * Hd;
    const size_t ZS = (size_t)BNW * Hd;
    if ((size_t)out_size >= YL + ZS)
        pool_kernel<<<BNW, 256>>>(yf, scorer_w, out + YL);
    stitch_kernel<<<(int)(YL / 256), 256>>>(yf, out);
    if ((size_t)out_size >= YL + ZS + BNW)
        bp_kernel<<<1, 64>>>(out + YL + ZS);
}

// round 15
// speedup vs baseline: 1.1393x; 1.1393x over previous
#include <cuda_runtime.h>
#include <cuda_bf16.h>
#include <cuda_fp16.h>
#include <math.h>
#include <stdint.h>

// ---------------- problem constants ----------------
#define Hd    1024
#define HEADS 16
#define DHd   64
#define Wn    256
#define Rn    128
#define Id    4096
#define Bn    2
#define Sn    4096
#define NW    31
#define BNW   (Bn*NW)       // 62
#define Tn    (BNW*Wn)      // 15872

typedef unsigned long long ull;

// ---- arch-specific ('a' target) feature gate for tcgen05 ------------------
#if !defined(__CUDA_ARCH__) || defined(__CUDA_ARCH_FEAT_SM103_ALL) || \
    defined(__CUDA_ARCH_FEAT_SM100_ALL) || defined(__CUDA_ARCH_SPECIFIC__) || \
    defined(__CUDA_ARCH_FAMILY_SPECIFIC__)
#define TC_OK 1
#else
#define TC_OK 0
#endif

// ---------------- tcgen05 / mbarrier helpers -------------------------------
__device__ __forceinline__ uint32_t smem_u32(const void* p) {
    uint32_t a;
    asm("{ .reg .u64 t; cvta.to.shared.u64 t, %1; cvt.u32.u64 %0, t; }" : "=r"(a) : "l"(p));
    return a;
}
#define SWZ(o)   ((o) ^ (((o) >> 3) & 0x70))
#define SWZ64(o) ((o) ^ (((o) >> 3) & 0x30))

#define MBAR_INIT(a, c) asm volatile("mbarrier.init.shared.b64 [%0], %1;" :: "r"(a), "r"(c) : "memory")
#define MBAR_WAIT(a, p) do { uint32_t _m = (a), _p = (p), _d;                                            \
    asm volatile("{\n\t.reg .pred P;\n\tmbarrier.try_wait.parity.acquire.cta.shared::cta.b64 P, [%1], %2;\n\tselp.b32 %0,1,0,P;\n\t}" \
        : "=r"(_d) : "r"(_m), "r"(_p) : "memory");                                                        \
    while (!_d) {                                                                                          \
        asm volatile("{\n\t.reg .pred P;\n\tmbarrier.try_wait.parity.acquire.cta.shared::cta.b64 P, [%1], %2, 0x989680;\n\tselp.b32 %0,1,0,P;\n\t}" \
            : "=r"(_d) : "r"(_m), "r"(_p) : "memory");                                                    \
    } } while (0)

// cp.async (LDGSTS) helpers
__device__ __forceinline__ void cp16(uint32_t dst, const void* src) {
    asm volatile("cp.async.cg.shared.global [%0], [%1], 16;" :: "r"(dst), "l"(src) : "memory");
}
#define CP_COMMIT() asm volatile("cp.async.commit_group;" ::: "memory")
#define CP_WAIT1()  asm volatile("cp.async.wait_group 1;" ::: "memory")
#define CP_WAIT0()  asm volatile("cp.async.wait_group 0;" ::: "memory")

#if TC_OK
#define TC_ALLOC(slot, n)  asm volatile("tcgen05.alloc.cta_group::1.sync.aligned.shared::cta.b32 [%0], %1;" :: "r"(slot), "r"(n) : "memory")
#define TC_DEALLOC(t, n)   asm volatile("tcgen05.dealloc.cta_group::1.sync.aligned.b32 %0, %1;" :: "r"(t), "r"(n))
#define TC_RELINQ()        asm volatile("tcgen05.relinquish_alloc_permit.cta_group::1.sync.aligned;")
#define TC_COMMIT(m)       asm volatile("tcgen05.commit.cta_group::1.mbarrier::arrive::one.shared::cluster.b64 [%0];" :: "r"(m) : "memory")
#define TC_FENCE_AFTER()   asm volatile("tcgen05.fence::after_thread_sync;" ::: "memory")
#define TC_FENCE_BEFORE()  asm volatile("tcgen05.fence::before_thread_sync;" ::: "memory")
#define TC_WAIT_LD()       asm volatile("tcgen05.wait::ld.sync.aligned;" ::: "memory")
#define TC_WAIT_ST()       asm volatile("tcgen05.wait::st.sync.aligned;" ::: "memory")
#define TC_LD_X32(r, a) \
    asm volatile("tcgen05.ld.sync.aligned.32x32b.x32.b32 " \
        "{%0,%1,%2,%3,%4,%5,%6,%7,%8,%9,%10,%11,%12,%13,%14,%15," \
        "%16,%17,%18,%19,%20,%21,%22,%23,%24,%25,%26,%27,%28,%29,%30,%31}, [%32];" \
        : "=r"((r)[0]),"=r"((r)[1]),"=r"((r)[2]),"=r"((r)[3]),"=r"((r)[4]),"=r"((r)[5]),"=r"((r)[6]),"=r"((r)[7]), \
          "=r"((r)[8]),"=r"((r)[9]),"=r"((r)[10]),"=r"((r)[11]),"=r"((r)[12]),"=r"((r)[13]),"=r"((r)[14]),"=r"((r)[15]), \
          "=r"((r)[16]),"=r"((r)[17]),"=r"((r)[18]),"=r"((r)[19]),"=r"((r)[20]),"=r"((r)[21]),"=r"((r)[22]),"=r"((r)[23]), \
          "=r"((r)[24]),"=r"((r)[25]),"=r"((r)[26]),"=r"((r)[27]),"=r"((r)[28]),"=r"((r)[29]),"=r"((r)[30]),"=r"((r)[31]) \
        : "r"(a))
#define TC_ST_X32(a, r) \
    asm volatile("tcgen05.st.sync.aligned.32x32b.x32.b32 [%0], " \
        "{%1,%2,%3,%4,%5,%6,%7,%8,%9,%10,%11,%12,%13,%14,%15,%16," \
        "%17,%18,%19,%20,%21,%22,%23,%24,%25,%26,%27,%28,%29,%30,%31,%32};" \
        :: "r"(a), \
           "r"((r)[0]),"r"((r)[1]),"r"((r)[2]),"r"((r)[3]),"r"((r)[4]),"r"((r)[5]),"r"((r)[6]),"r"((r)[7]), \
           "r"((r)[8]),"r"((r)[9]),"r"((r)[10]),"r"((r)[11]),"r"((r)[12]),"r"((r)[13]),"r"((r)[14]),"r"((r)[15]), \
           "r"((r)[16]),"r"((r)[17]),"r"((r)[18]),"r"((r)[19]),"r"((r)[20]),"r"((r)[21]),"r"((r)[22]),"r"((r)[23]), \
           "r"((r)[24]),"r"((r)[25]),"r"((r)[26]),"r"((r)[27]),"r"((r)[28]),"r"((r)[29]),"r"((r)[30]),"r"((r)[31]) \
        : "memory")
#else
#define TC_ALLOC(slot, n)  do {} while (0)
#define TC_DEALLOC(t, n)   do {} while (0)
#define TC_RELINQ()        do {} while (0)
#define TC_COMMIT(m)       do {} while (0)
#define TC_FENCE_AFTER()   do {} while (0)
#define TC_FENCE_BEFORE()  do {} while (0)
#define TC_WAIT_LD()       do {} while (0)
#define TC_WAIT_ST()       do {} while (0)
#define TC_LD_X32(r, a)    do { _Pragma("unroll") for (int _i = 0; _i < 32; _i++) (r)[_i] = 0u; } while (0)
#define TC_ST_X32(a, r)    do { (void)(a); (void)(r)[0]; } while (0)
#endif
#define FENCE_ASYNC()      asm volatile("fence.proxy.async.shared::cta;" ::: "memory")

__device__ __forceinline__ void mma_ss_f16(uint32_t d, ull ad, ull bd, uint32_t idesc, int acc) {
#if TC_OK
    asm volatile("{\n\t.reg .pred p;\n\tsetp.ne.u32 p, %5, 0;\n\t"
        "tcgen05.mma.cta_group::1.kind::f16 [%0], %1, %2, %3, {%4,%4,%4,%4}, p;\n\t}"
        :: "r"(d), "l"(ad), "l"(bd), "r"(idesc), "r"(0u), "r"(acc) : "memory");
#endif
}
__device__ __forceinline__ void mma_ts_f16(uint32_t d, uint32_t a, ull bd, uint32_t idesc, int acc) {
#if TC_OK
    asm volatile("{\n\t.reg .pred p;\n\tsetp.ne.u32 p, %5, 0;\n\t"
        "tcgen05.mma.cta_group::1.kind::f16 [%0], [%1], %2, %3, {%4,%4,%4,%4}, p;\n\t}"
        :: "r"(d), "r"(a), "l"(bd), "r"(idesc), "r"(0u), "r"(acc) : "memory");
#endif
}

// SW128 K-major smem descriptor (LBO=1, SBO=64)
static __device__ __forceinline__ ull make_desc(uint32_t addr) {
    return (2ULL << 61) | (1ULL << 46) | (64ULL << 32) | (1ULL << 16)
         | ((ull)(addr >> 4) & 0x3FFF);
}
// SW64 K-major smem descriptor (LBO=1, SBO=32, layout=4) — validated R9
static __device__ __forceinline__ ull make_desc64(uint32_t addr) {
    return (4ULL << 61) | (1ULL << 46) | (32ULL << 32) | (1ULL << 16)
         | ((ull)(addr >> 4) & 0x3FFF);
}

__device__ __forceinline__ void bfsplit2(float a, float b, uint32_t& h, uint32_t& l) {
    __nv_bfloat162 hh, ll;
    hh.x = __float2bfloat16(a); hh.y = __float2bfloat16(b);
    ll.x = __float2bfloat16(a - __bfloat162float(hh.x));
    ll.y = __float2bfloat16(b - __bfloat162float(hh.y));
    h = *(uint32_t*)&hh; l = *(uint32_t*)&ll;
}

// ---------------- scratch --------------------------------------------------
__device__ float g_qkv[(size_t)Tn * 3 * Hd];
__device__ float g_y  [(size_t)Tn * Hd];
__device__ float g_yf [(size_t)Tn * Hd];
__device__ __nv_bfloat16 g_nh[(size_t)Tn * Hd], g_nl[(size_t)Tn * Hd];
__device__ __nv_bfloat16 g_oh[(size_t)Tn * Hd], g_ol[(size_t)Tn * Hd];
__device__ __nv_bfloat16 g_ch[(size_t)Tn * Id], g_cl[(size_t)Tn * Id];
// dedicated weight buffers (hi/lo) per GEMM — split once, up front
__device__ __nv_bfloat16 g_wqh[(size_t)3 * Hd * Hd], g_wql[(size_t)3 * Hd * Hd];
__device__ __nv_bfloat16 g_woh[(size_t)Hd * Hd],     g_wol[(size_t)Hd * Hd];
__device__ __nv_bfloat16 g_wgh[(size_t)2 * Id * Hd], g_wgl[(size_t)2 * Id * Hd];
__device__ __nv_bfloat16 g_wdh[(size_t)Hd * Id],     g_wdl[(size_t)Hd * Id];

// ---------------- merged weight split (all four weights, one launch) -------
#define NQ (3 * Hd * Hd)       // 3,145,728
#define NO (Hd * Hd)           // 1,048,576
#define NG (2 * Id * Hd)       // 8,388,608
#define ND (Hd * Id)           // 4,194,304

__global__ void split_all_kernel(const float* __restrict__ qkv_w,
                                 const float* __restrict__ o_w,
                                 const float* __restrict__ gate_up_w,
                                 const float* __restrict__ down_w) {
    long i = (long)blockIdx.x * 256 + threadIdx.x;
    float v;
    __nv_bfloat16* hi;
    __nv_bfloat16* lo;
    long j;
    if (i < NQ) {
        j = i; v = qkv_w[j]; hi = g_wqh; lo = g_wql;
    } else if (i < (long)NQ + NO) {
        j = i - NQ; v = o_w[j]; hi = g_woh; lo = g_wol;
    } else if (i < (long)NQ + NO + NG) {
        j = i - NQ - NO;
        // gate_up with row interleave: out row 2i=gate_i, 2i+1=up_i
        int row = (int)(j >> 10), col = (int)(j & (Hd - 1));
        int src = (row & 1) ? (Id + (row >> 1)) : (row >> 1);
        v = gate_up_w[(size_t)src * Hd + col]; hi = g_wgh; lo = g_wgl;
    } else {
        j = i - NQ - NO - NG;
        if (j >= ND) return;
        v = down_w[j]; hi = g_wdh; lo = g_wdl;
    }
    __nv_bfloat16 h = __float2bfloat16(v);
    hi[j] = h;
    lo[j] = __float2bfloat16(v - __bfloat162float(h));
}

// ---------------- RMSNorm (optional window gather), writes bf16 split -----
template<bool GATHER>
__global__ void rmsnorm_kernel(const float* __restrict__ src,
                               const float* __restrict__ w,
                               __nv_bfloat16* __restrict__ oh,
                               __nv_bfloat16* __restrict__ ol) {
    int t = blockIdx.x;
    const float* row;
    if (GATHER) {
        int bn = t >> 8, ww = t & 255;
        int b = bn / NW, n = bn - b * NW;
        row = src + (size_t)(b * Sn + n * Rn + ww) * Hd;
    } else {
        row = src + (size_t)t * Hd;
    }
    int tid = threadIdx.x;
    float ss = 0.f;
    for (int h = tid; h < Hd; h += 256) { float v = row[h]; ss += v * v; }
    __shared__ float red[8];
    #pragma unroll
    for (int o = 16; o; o >>= 1) ss += __shfl_xor_sync(~0u, ss, o);
    if ((tid & 31) == 0) red[tid >> 5] = ss;
    __syncthreads();
    if (tid < 8) {
        float v = red[tid];
        #pragma unroll
        for (int o = 4; o; o >>= 1) v += __shfl_xor_sync(0xff, v, o);
        if (tid == 0) red[0] = v;
    }
    __syncthreads();
    float rms = rsqrtf(red[0] * (1.f / Hd) + 1e-5f);
    for (int h = tid; h < Hd; h += 256) {
        float v = row[h] * rms * w[h];
        __nv_bfloat16 hv = __float2bfloat16(v);
        oh[(size_t)t * Hd + h] = hv;
        ol[(size_t)t * Hd + h] = __float2bfloat16(v - __bfloat162float(hv));
    }
}

// ---------------- tcgen05 bf16-split GEMM: 256x256 tile, Kc=32, 3 stages ---
// (R11-validated pipeline: CP_WAIT + syncthreads, per-slot done mbars)
// EPI: 0 none, 1 +=Res, 2 +=gathered x, 3 swiglu->bf16 split, 4 rope on q/k
#define GBUF  65536
#define GSMEM (1024 + 3 * GBUF)

__device__ __forceinline__ void bg_load32(
    const __nv_bfloat16* Ah, const __nv_bfloat16* Al,
    const __nv_bfloat16* Bh, const __nv_bfloat16* Bl,
    int bm, int bn, int K, int k0, uint32_t stu, int tid) {
    const int strideA = K >> 3;                 // uint4 per row
    {
        const uint4* gh = (const uint4*)(Ah + (size_t)bm * K + k0);
        const uint4* gl = (const uint4*)(Al + (size_t)bm * K + k0);
        #pragma unroll
        for (int it = 0; it < 8; it++) {
            int v = (it << 7) + tid;            // 0..1023
            int row = v >> 2, c16 = v & 3;      // 256 rows x 4 uint4
            uint32_t so = SWZ64(row * 64 + c16 * 16);
            cp16(stu + so,         gh + (size_t)row * strideA + c16);
            cp16(stu + 16384 + so, gl + (size_t)row * strideA + c16);
        }
    }
    {
        const uint4* gh = (const uint4*)(Bh + (size_t)bn * K + k0);
        const uint4* gl = (const uint4*)(Bl + (size_t)bn * K + k0);
        #pragma unroll
        for (int it = 0; it < 8; it++) {
            int v = (it << 7) + tid;
            int row = v >> 2, c16 = v & 3;
            uint32_t so = SWZ64(row * 64 + c16 * 16);
            cp16(stu + 32768 + so, gh + (size_t)row * strideA + c16);
            cp16(stu + 49152 + so, gl + (size_t)row * strideA + c16);
        }
    }
}

template<int EPI>
__global__ void __launch_bounds__(128, 1)
bgemm_kernel(const __nv_bfloat16* __restrict__ Ah, const __nv_bfloat16* __restrict__ Al,
             const __nv_bfloat16* __restrict__ Bh, const __nv_bfloat16* __restrict__ Bl,
             float* __restrict__ C, const float* __restrict__ Res,
             __nv_bfloat16* __restrict__ Oh, __nv_bfloat16* __restrict__ Ol,
             const int* __restrict__ pos, int Nc, int K) {
    extern __shared__ __align__(1024) char smem[];
    const int tid = threadIdx.x, wid = tid >> 5, lid = tid & 31;
    const int bm = blockIdx.y << 8, bn = blockIdx.x << 8;
    uint32_t sb = smem_u32(smem);

    if (tid == 0) {
        #pragma unroll
        for (int s = 0; s < 3; s++) MBAR_INIT(sb + 8 + 8 * s, 1);
    }
    if (wid == 0) TC_ALLOC(sb, 512);
    __syncthreads();
    uint32_t tmem;
    asm("ld.shared.b32 %0, [%1];" : "=r"(tmem) : "r"(sb));

    // f16 kind, bf16 in, f32 out, N=256, M=128
    const uint32_t IDESC = (1u << 4) | (1u << 7) | (1u << 10) | (32u << 17) | (8u << 24);
    const int KCn = K >> 5;                    // Kc = 32
    uint32_t mph = 0;                           // per-slot mbar phase bits

    // prologue: load chunks 0,1 into slots 0,1
    bg_load32(Ah, Al, Bh, Bl, bm, bn, K, 0,  sb + 1024,        tid); CP_COMMIT();
    if (KCn > 1) {
        bg_load32(Ah, Al, Bh, Bl, bm, bn, K, 32, sb + 1024 + GBUF, tid); CP_COMMIT();
    }

    for (int c = 0; c < KCn; c++) {
        int s = c % 3;
        uint32_t stu = sb + 1024 + s * GBUF;
        if (c + 1 < KCn) CP_WAIT1(); else CP_WAIT0();
        __syncthreads();
        if (tid == 0) {
            FENCE_ASYNC();
            ull dAh = make_desc64(stu);
            ull dAl = make_desc64(stu + 16384);
            ull dBh = make_desc64(stu + 32768);
            ull dBl = make_desc64(stu + 49152);
            #pragma unroll
            for (int t = 0; t < 2; t++) {
                uint32_t D = tmem + (t << 8);
                ull at = (ull)(t * 512);        // Mtile1 rows at +8192B
                #pragma unroll
                for (int ks = 0; ks < 2; ks++) {
                    ull ao = at + ks * 2;
                    ull bo = (ull)(ks * 2);
                    int first = (c == 0 && ks == 0) ? 0 : 1;
                    mma_ss_f16(D, dAh + ao, dBh + bo, IDESC, first);
                    mma_ss_f16(D, dAh + ao, dBl + bo, IDESC, 1);
                    mma_ss_f16(D, dAl + ao, dBh + bo, IDESC, 1);
                }
            }
            TC_COMMIT(sb + 8 + 8 * s);
        }
        // prefetch chunk c+2 into slot (c+2)%3; its prior occupant was chunk c-1
        if (c + 2 < KCn) {
            int s2 = (c + 2) % 3;
            if (c >= 1) {
                MBAR_WAIT(sb + 8 + 8 * s2, (mph >> s2) & 1);
                mph ^= 1u << s2;
            }
            bg_load32(Ah, Al, Bh, Bl, bm, bn, K, (c + 2) << 5,
                      sb + 1024 + s2 * GBUF, tid);
            CP_COMMIT();
        }
    }
    // final: wait last chunk's commit (covers all prior MMAs)
    {
        int s3 = (KCn - 1) % 3;
        MBAR_WAIT(sb + 8 + 8 * s3, (mph >> s3) & 1);
    }
    TC_FENCE_AFTER();

    // epilogue: 2 Mtiles x (4 warps x 32 rows); N=256 in 8 groups of 32
    #pragma unroll 1
    for (int t = 0; t < 2; t++) {
        int row = bm + (t << 7) + (wid << 5) + lid;
        if (EPI == 4) {
            float snt[32], cst[32];
            {
                int bnw = row >> 8, ww = row & 255;
                int b = bnw / NW, n = bnw - b * NW;
                float p = (float)pos[b * Sn + n * Rn + ww];
                #pragma unroll
                for (int d = 0; d < 32; d++) {
                    float inv = powf(10000.f, -(2.f * d) / 64.f);
                    sincosf(p * inv, &snt[d], &cst[d]);
                }
            }
            float* cbase = C + (size_t)row * Nc + bn;
            #pragma unroll 1
            for (int hh = 0; hh < 4; hh++) {
                uint32_t r0[32], r1[32];
                TC_LD_X32(r0, tmem + (t << 8) + hh * 64);
                TC_LD_X32(r1, tmem + (t << 8) + hh * 64 + 32);
                TC_WAIT_LD();
                float a[32], b[32];
                #pragma unroll
                for (int j = 0; j < 32; j++) { a[j] = __uint_as_float(r0[j]); b[j] = __uint_as_float(r1[j]); }
                if (bn + hh * 64 < 2048) {
                    #pragma unroll
                    for (int d = 0; d < 32; d++) {
                        float q1 = a[d], q2 = b[d];
                        a[d] = q1 * cst[d] - q2 * snt[d];
                        b[d] = q2 * cst[d] + q1 * snt[d];
                    }
                }
                #pragma unroll
                for (int j = 0; j < 32; j += 4) {
                    float4 o0 = {a[j], a[j+1], a[j+2], a[j+3]};
                    float4 o1 = {b[j], b[j+1], b[j+2], b[j+3]};
                    *(float4*)(cbase + hh * 64 + j) = o0;
                    *(float4*)(cbase + hh * 64 + 32 + j) = o1;
                }
            }
        } else if (EPI == 3) {
            int outb = (bn >> 1);
            __nv_bfloat16* chb = Oh + (size_t)row * Id + outb;
            __nv_bfloat16* clb = Ol + (size_t)row * Id + outb;
            #pragma unroll 1
            for (int g = 0; g < 8; g++) {
                uint32_t r[32];
                TC_LD_X32(r, tmem + (t << 8) + g * 32);
                TC_WAIT_LD();
                __nv_bfloat162 ph[8], pl[8];
                #pragma unroll
                for (int m = 0; m < 16; m++) {
                    float gv = __uint_as_float(r[2 * m]);
                    float uv = __uint_as_float(r[2 * m + 1]);
                    float v = uv * (gv / (1.f + expf(-gv)));
                    __nv_bfloat16 hv = __float2bfloat16(v);
                    ((__nv_bfloat16*)ph)[m] = hv;
                    ((__nv_bfloat16*)pl)[m] = __float2bfloat16(v - __bfloat162float(hv));
                }
                #pragma unroll
                for (int m2 = 0; m2 < 8; m2++) {
                    ((__nv_bfloat162*)(chb + g * 16))[m2] = ph[m2];
                    ((__nv_bfloat162*)(clb + g * 16))[m2] = pl[m2];
                }
            }
        } else {
            const float* rbase = nullptr;
            if (EPI == 1) rbase = Res + (size_t)row * Nc + bn;
            if (EPI == 2) {
                int bnw = row >> 8, ww = row & 255;
                int b = bnw / NW, n = bnw - b * NW;
                rbase = Res + (size_t)(b * Sn + n * Rn + ww) * Hd + bn;
            }
            float* cbase = C + (size_t)row * Nc + bn;
            #pragma unroll 1
            for (int g = 0; g < 8; g++) {
                uint32_t r[32];
                TC_LD_X32(r, tmem + (t << 8) + g * 32);
                TC_WAIT_LD();
                float rv[32];
                #pragma unroll
                for (int j = 0; j < 32; j++) rv[j] = __uint_as_float(r[j]);
                if (EPI) {
                    #pragma unroll
                    for (int j = 0; j < 32; j++) rv[j] += rbase[g * 32 + j];
                }
                #pragma unroll
                for (int j = 0; j < 32; j += 4) {
                    float4 o = {rv[j], rv[j+1], rv[j+2], rv[j+3]};
                    *(float4*)(cbase + g * 32 + j) = o;
                }
            }
        }
    }
    __syncthreads();
    if (wid == 0) { TC_RELINQ(); TC_DEALLOC(tmem, 512); }
}

// ---------------- tensor-core windowed causal attention --------------------
// V stored as single fp16 (quantization error averages over softmax sum);
// P-V uses one product -> half the PV MMA dispatches vs the split version.
#define AQH  1024
#define AQL  (AQH + 32768)
#define AKH  (AQL + 32768)
#define AKL  (AKH + 32768)
#define AVH  (AKL + 32768)
#define AQQ  (AVH + 32768)            // 256 floats
#define AKN  (AQQ + 1024)             // 8 floats
#define ATTN_SMEM (AKN + 64)

__global__ void __launch_bounds__(256, 1)
attn_kernel(const float* __restrict__ qkv,
            __nv_bfloat16* __restrict__ outh, __nv_bfloat16* __restrict__ outl) {
    int bnw = blockIdx.x, h = blockIdx.y;
    extern __shared__ __align__(1024) char smem[];
    uint32_t sb = smem_u32(smem);
    int tid = threadIdx.x, wid = tid >> 5, lid = tid & 31;
    int t0 = bnw * Wn;
    float* qqA = (float*)(smem + AQQ);
    float* knW = (float*)(smem + AKN);

    if (tid == 0) { MBAR_INIT(sb + 8, 1); MBAR_INIT(sb + 16, 1); }
    if (wid == 0) TC_ALLOC(sb, 512);
    __syncthreads();
    uint32_t tmem;
    asm("ld.shared.b32 %0, [%1];" : "=r"(tmem) : "r"(sb));

    {
        const float4* qrow = (const float4*)(qkv + (size_t)(t0 + tid) * (3 * Hd) + h * DHd);
        const float4* krow = qrow + (Hd / 4);
        const float4* vrow = qrow + (2 * Hd / 4);
        float qq = 0.f, kk = 0.f;
        #pragma unroll
        for (int g = 0; g < 8; g++) {
            float4 a = qrow[g * 2], b = qrow[g * 2 + 1];
            qq += a.x*a.x + a.y*a.y + a.z*a.z + a.w*a.w + b.x*b.x + b.y*b.y + b.z*b.z + b.w*b.w;
            uint4 hi, lo;
            bfsplit2(a.x, a.y, hi.x, lo.x); bfsplit2(a.z, a.w, hi.y, lo.y);
            bfsplit2(b.x, b.y, hi.z, lo.z); bfsplit2(b.z, b.w, hi.w, lo.w);
            uint32_t so = SWZ(tid * 128 + g * 16);
            *(uint4*)(smem + AQH + so) = hi;
            *(uint4*)(smem + AQL + so) = lo;
        }
        #pragma unroll
        for (int g = 0; g < 8; g++) {
            float4 a = krow[g * 2], b = krow[g * 2 + 1];
            kk += a.x*a.x + a.y*a.y + a.z*a.z + a.w*a.w + b.x*b.x + b.y*b.y + b.z*b.z + b.w*b.w;
            uint4 hi, lo;
            bfsplit2(a.x, a.y, hi.x, lo.x); bfsplit2(a.z, a.w, hi.y, lo.y);
            bfsplit2(b.x, b.y, hi.z, lo.z); bfsplit2(b.z, b.w, hi.w, lo.w);
            uint32_t so = SWZ(tid * 128 + g * 16);
            *(uint4*)(smem + AKH + so) = hi;
            *(uint4*)(smem + AKL + so) = lo;
        }
        // V transpose, single fp16: panels of 64 keys x 64 dims
        char* vhB = smem + AVH + (tid >> 6) * 8192;
        int jj2 = (tid & 63) * 2;
        #pragma unroll
        for (int d4 = 0; d4 < 16; d4++) {
            float4 v = vrow[d4];
            float vv[4] = {v.x, v.y, v.z, v.w};
            #pragma unroll
            for (int e = 0; e < 4; e++) {
                int d = d4 * 4 + e;
                *(__half*)(vhB + SWZ(d * 128 + jj2)) = __float2half_rn(vv[e]);
            }
        }
        qqA[tid] = qq;
        #pragma unroll
        for (int o = 16; o; o >>= 1) kk = fmaxf(kk, __shfl_xor_sync(~0u, kk, o));
        if (lid == 0) knW[wid] = kk;
    }
    __syncthreads();

    if (tid == 0) {
        FENCE_ASYNC();
        ull qh = make_desc(sb + AQH), ql = make_desc(sb + AQL);
        ull kh = make_desc(sb + AKH), kl = make_desc(sb + AKL);
        const uint32_t IDS = (1u << 4) | (1u << 7) | (1u << 10) | (16u << 17) | (8u << 24);
        #pragma unroll
        for (int t = 0; t < 2; t++) {
            #pragma unroll
            for (int n = 0; n < 2; n++) {
                uint32_t D = tmem + t * 256 + n * 128;
                #pragma unroll
                for (int ks = 0; ks < 4; ks++) {
                    ull ao = (ull)(t * 1024 + ks * 2);
                    ull bo = (ull)(n * 1024 + ks * 2);
                    mma_ss_f16(D, qh + ao, kh + bo, IDS, ks > 0);
                    mma_ss_f16(D, qh + ao, kl + bo, IDS, 1);
                    mma_ss_f16(D, ql + ao, kh + bo, IDS, 1);
                }
            }
        }
        TC_COMMIT(sb + 8);
    }
    MBAR_WAIT(sb + 8, 0);
    TC_FENCE_AFTER();

    int t = wid >> 2;
    int qi = t * 128 + (wid & 3) * 32 + lid;
    float KM = knW[0];
    #pragma unroll
    for (int w = 1; w < 8; w++) KM = fmaxf(KM, knW[w]);
    float mx = sqrtf(qqA[qi] * KM) * 0.125f;
    float l = 0.f;
    uint32_t woff = (uint32_t)(wid & 3) << 21;
    #pragma unroll 1
    for (int c = 0; c < 4; c++) {
        uint32_t r0[32], r1[32];
        TC_LD_X32(r0, tmem + t * 256 + c * 64);
        TC_LD_X32(r1, tmem + t * 256 + c * 64 + 32);
        TC_WAIT_LD();
        float pa[64];
        #pragma unroll
        for (int i = 0; i < 32; i++) {
            float s = __uint_as_float(r0[i]);
            float p = __expf(fmaf(s, 0.125f, -mx));
            p = (c * 64 + i <= qi) ? p : 0.f;
            l += p; pa[i] = p;
        }
        #pragma unroll
        for (int i = 0; i < 32; i++) {
            float s = __uint_as_float(r1[i]);
            float p = __expf(fmaf(s, 0.125f, -mx));
            p = (c * 64 + 32 + i <= qi) ? p : 0.f;
            l += p; pa[32 + i] = p;
        }
        uint32_t pr[32];
        #pragma unroll
        for (int i = 0; i < 32; i++) {
            __half2 h2 = __float22half2_rn(make_float2(pa[2 * i], pa[2 * i + 1]));
            pr[i] = *(uint32_t*)&h2;
        }
        TC_ST_X32(tmem + t * 256 + c * 32 + woff, pr);
    }
    TC_WAIT_ST();
    TC_FENCE_BEFORE();
    __syncthreads();

    if (tid == 0) {
        TC_FENCE_AFTER();
        ull vh = make_desc(sb + AVH);
        const uint32_t IDP = (1u << 4) | (8u << 17) | (8u << 24);
        #pragma unroll
        for (int tt = 0; tt < 2; tt++) {
            uint32_t D = tmem + tt * 256 + 128;
            #pragma unroll
            for (int s = 0; s < 16; s++) {
                ull bo = (ull)((s >> 2) * 512 + (s & 3) * 2);
                uint32_t A = tmem + tt * 256 + s * 8;
                mma_ts_f16(D, A, vh + bo, IDP, s > 0);
            }
        }
        TC_COMMIT(sb + 16);
    }
    MBAR_WAIT(sb + 16, 0);
    TC_FENCE_AFTER();

    {
        uint32_t o0[32], o1[32];
        TC_LD_X32(o0, tmem + t * 256 + 128);
        TC_LD_X32(o1, tmem + t * 256 + 160);
        TC_WAIT_LD();
        float inv = 1.f / l;
        uint32_t* ohp = (uint32_t*)(outh + (size_t)(t0 + qi) * Hd + h * DHd);
        uint32_t* olp = (uint32_t*)(outl + (size_t)(t0 + qi) * Hd + h * DHd);
        #pragma unroll
        for (int i = 0; i < 16; i++) {
            uint32_t hu, lu;
            bfsplit2(__uint_as_float(o0[2 * i]) * inv, __uint_as_float(o0[2 * i + 1]) * inv, hu, lu);
            ohp[i] = hu; olp[i] = lu;
        }
        #pragma unroll
        for (int i = 0; i < 16; i++) {
            uint32_t hu, lu;
            bfsplit2(__uint_as_float(o1[2 * i]) * inv, __uint_as_float(o1[2 * i + 1]) * inv, hu, lu);
            ohp[16 + i] = hu; olp[16 + i] = lu;
        }
    }
    __syncthreads();
    if (wid == 0) { TC_RELINQ(); TC_DEALLOC(tmem, 512); }
}

// ---------------- per-window attn-pool -------------------------------------
__global__ void pool_kernel(const float* __restrict__ y, const float* __restrict__ sw,
                            float* __restrict__ z) {
    int bn = blockIdx.x, tid = threadIdx.x;
    __shared__ float alpha[256];
    __shared__ float tmp[256];
    const float4* row = (const float4*)(y + (size_t)(bn * Wn + tid) * Hd);
    const float4* wv = (const float4*)sw;
    float s = 0.f;
    for (int i = 0; i < Hd / 4; i++) {
        float4 a = row[i], b = wv[i];
        s += a.x * b.x + a.y * b.y + a.z * b.z + a.w * b.w;
    }
    tmp[tid] = s; __syncthreads();
    for (int o = 128; o; o >>= 1) { if (tid < o) tmp[tid] = fmaxf(tmp[tid], tmp[tid + o]); __syncthreads(); }
    float mx = tmp[0]; __syncthreads();
    float e = expf(s - mx);
    tmp[tid] = e; __syncthreads();
    for (int o = 128; o; o >>= 1) { if (tid < o) tmp[tid] += tmp[tid + o]; __syncthreads(); }
    alpha[tid] = e / tmp[0];
    __syncthreads();
    for (int hh = tid; hh < Hd; hh += 256) {
        float a = 0.f;
        for (int w2 = 0; w2 < Wn; w2++)
            a = fmaf(alpha[w2], y[(size_t)(bn * Wn + w2) * Hd + hh], a);
        z[(size_t)bn * Hd + hh] = a;
    }
}

// ---------------- triangular overlap-add stitch ----------------------------
__global__ void stitch_kernel(const float* __restrict__ yf, float* __restrict__ out) {
    size_t id = (size_t)blockIdx.x * 256 + threadIdx.x;
    int hcol = (int)(id & (Hd - 1));
    int s = (int)((id >> 10) & (Sn - 1));
    int b = (int)(id >> 22);
    int nhi = min(NW - 1, s >> 7);
    int nlo = max(0, (s - Rn) >> 7);
    float acc = 0.f, wsum = 0.f;
    for (int n = nlo; n <= nhi; n++) {
        int w2 = s - n * Rn;
        float blend = (w2 < 128 ? (float)w2 : (float)(256 - w2)) * (1.f / 128.f);
        acc = fmaf(blend, yf[(size_t)((b * NW + n) * Wn + w2) * Hd + hcol], acc);
        wsum += blend;
    }
    out[id] = acc / (wsum + 1e-8f);
}

__global__ void bp_kernel(float* out) {
    int i = threadIdx.x;
    if (i < BNW) out[i] = (float)((i % NW) * Rn + (Wn - 1));
}

// ---------------- launcher --------------------------------------------------
extern "C" void kernel_launch(void* const* d_in, const int* in_sizes, int n_in,
                              void* d_out, int out_size) {
    const float* x          = (const float*)d_in[0];
    const int*   pos        = (const int*)  d_in[1];
    const float* in_norm_w  = (const float*)d_in[2];
    const float* mlp_norm_w = (const float*)d_in[3];
    const float* qkv_w      = (const float*)d_in[4];
    const float* o_w        = (const float*)d_in[5];
    const float* gate_up_w  = (const float*)d_in[6];
    const float* down_w     = (const float*)d_in[7];
    const float* scorer_w   = (const float*)d_in[8];
    float* out = (float*)d_out;

    float *qkv, *y, *yf;
    __nv_bfloat16 *nh, *nl, *oh, *ol, *ch, *cl;
    __nv_bfloat16 *wqh, *wql, *woh, *wol, *wgh, *wgl, *wdh, *wdl;
    cudaGetSymbolAddress((void**)&qkv, g_qkv);
    cudaGetSymbolAddress((void**)&y,   g_y);
    cudaGetSymbolAddress((void**)&yf,  g_yf);
    cudaGetSymbolAddress((void**)&nh,  g_nh);
    cudaGetSymbolAddress((void**)&nl,  g_nl);
    cudaGetSymbolAddress((void**)&oh,  g_oh);
    cudaGetSymbolAddress((void**)&ol,  g_ol);
    cudaGetSymbolAddress((void**)&ch,  g_ch);
    cudaGetSymbolAddress((void**)&cl,  g_cl);
    cudaGetSymbolAddress((void**)&wqh, g_wqh);
    cudaGetSymbolAddress((void**)&wql, g_wql);
    cudaGetSymbolAddress((void**)&woh, g_woh);
    cudaGetSymbolAddress((void**)&wol, g_wol);
    cudaGetSymbolAddress((void**)&wgh, g_wgh);
    cudaGetSymbolAddress((void**)&wgl, g_wgl);
    cudaGetSymbolAddress((void**)&wdh, g_wdh);
    cudaGetSymbolAddress((void**)&wdl, g_wdl);

    cudaFuncSetAttribute(attn_kernel, cudaFuncAttributeMaxDynamicSharedMemorySize, ATTN_SMEM);
    cudaFuncSetAttribute(bgemm_kernel<1>, cudaFuncAttributeMaxDynamicSharedMemorySize, GSMEM);
    cudaFuncSetAttribute(bgemm_kernel<2>, cudaFuncAttributeMaxDynamicSharedMemorySize, GSMEM);
    cudaFuncSetAttribute(bgemm_kernel<3>, cudaFuncAttributeMaxDynamicSharedMemorySize, GSMEM);
    cudaFuncSetAttribute(bgemm_kernel<4>, cudaFuncAttributeMaxDynamicSharedMemorySize, GSMEM);

    const int MB = Tn / 256;   // 62
    const long NALL = (long)NQ + NO + NG + ND;   // 16,777,216

    // 0) split ALL weights once, up front (independent of everything else)
    split_all_kernel<<<(int)((NALL + 255) / 256), 256>>>(qkv_w, o_w, gate_up_w, down_w);
    // 1) gather + input RMSNorm -> split
    rmsnorm_kernel<true><<<Tn, 256>>>(x, in_norm_w, nh, nl);
    // 2) QKV projection + fused RoPE
    bgemm_kernel<4><<<dim3(3 * Hd / 256, MB), 128, GSMEM>>>(nh, nl, wqh, wql, qkv, nullptr, nullptr, nullptr, pos, 3 * Hd, Hd);
    // 3) tensor-core attention -> split
    attn_kernel<<<dim3(BNW, HEADS), 256, ATTN_SMEM>>>(qkv, oh, ol);
    // 4) O projection + residual(gathered x)
    bgemm_kernel<2><<<dim3(Hd / 256, MB), 128, GSMEM>>>(oh, ol, woh, wol, y, x, nullptr, nullptr, nullptr, Hd, Hd);
    // 5) MLP RMSNorm -> split
    rmsnorm_kernel<false><<<Tn, 256>>>(y, mlp_norm_w, nh, nl);
    // 6) gate_up (interleaved rows) + fused SwiGLU -> bf16 split act
    bgemm_kernel<3><<<dim3(2 * Id / 256, MB), 128, GSMEM>>>(nh, nl, wgh, wgl, nullptr, nullptr, ch, cl, nullptr, 2 * Id, Hd);
    // 7) down + residual(y)
    bgemm_kernel<1><<<dim3(Hd / 256, MB), 128, GSMEM>>>(ch, cl, wdh, wdl, yf, y, nullptr, nullptr, nullptr, Hd, Id);

    const size_t YL = (size_t)Bn * Sn * Hd;
    const size_t ZS = (size_t)BNW * Hd;
    if ((size_t)out_size >= YL + ZS)
        pool_kernel<<<BNW, 256>>>(yf, scorer_w, out + YL);
    stitch_kernel<<<(int)(YL / 256), 256>>>(yf, out);
    if ((size_t)out_size >= YL + ZS + BNW)
        bp_kernel<<<1, 64>>>(out + YL + ZS);
}